// round 3
// baseline (speedup 1.0000x reference)
#include <cuda_runtime.h>
#include <cstddef>

#define NE 1600000
#define NV 100000
#define NLAYER 20
#define BN_EPS 1e-5f
#define NT 256
#define NBLK 1563               // ceil(NE/4 / 256)
#define GS_STRIDE (NBLK * NT)
#define CHUNK 1024
#define NCH 98                  // ceil(NV / 1024)

// ---------------- constant weights ----------------
struct CW {
    float we_w1[36], we_b1[4], we_g1[4], we_be1[4], we_w2[12], we_b2[3];
    float wv_w1[18], wv_b1[3], wv_g1[3], wv_be1[3], wv_w2[9], wv_b2[3];
    float ow1[9], ob1[3], og[3], obe[3], ow2[6], ob2[2];
};
__constant__ CW cw;

// ---------------- persistent device state ----------------
__device__ float4 g_M[2][NV];
__device__ float  g_Hs[NE * 3];     // H in dst-sorted order
__device__ float4 g_Y[NE];          // pre-BN e-MLP output (sorted order)
__device__ float  g_Z[NE * 3];      // z scratch (sorted order)
__device__ int    g_srcs[NE];       // permuted src
__device__ int    g_dsts[NE];       // permuted dst
__device__ int    g_perm[NE];       // sorted position -> original edge id
__device__ int    g_hist[NV];       // also reused as nothing else
__device__ int    g_cursor[NV];
__device__ int    g_csum[NCH];
__device__ float  g_stats[22 * 16];

__device__ __forceinline__ float wsum(float v) {
#pragma unroll
    for (int o = 16; o; o >>= 1) v += __shfl_xor_sync(0xffffffffu, v, o);
    return v;
}

template <int K>
__device__ __forceinline__ void block_atomic_add(float* dst, float* v) {
#pragma unroll
    for (int j = 0; j < K; j++) v[j] = wsum(v[j]);
    __shared__ float bs[K];
    if (threadIdx.x < K) bs[threadIdx.x] = 0.f;
    __syncthreads();
    if ((threadIdx.x & 31) == 0) {
#pragma unroll
        for (int j = 0; j < K; j++) atomicAdd(&bs[j], v[j]);
    }
    __syncthreads();
    if (threadIdx.x < K) atomicAdd(&dst[threadIdx.x], bs[threadIdx.x]);
    __syncthreads();
}

// ================= preprocessing: counting sort by dst =================
__global__ void __launch_bounds__(NT)
k_hist(const int* __restrict__ dst) {
    int t = blockIdx.x * NT + threadIdx.x;
    for (int e = t; e < NE; e += GS_STRIDE) atomicAdd(&g_hist[__ldg(dst + e)], 1);
}

// per-chunk exclusive scan; writes exclusive values into g_cursor, chunk totals into g_csum
__global__ void __launch_bounds__(CHUNK)
k_scan1() {
    __shared__ int sh[CHUNK];
    int tid = threadIdx.x;
    int idx = blockIdx.x * CHUNK + tid;
    int v = (idx < NV) ? g_hist[idx] : 0;
    sh[tid] = v;
    __syncthreads();
    for (int off = 1; off < CHUNK; off <<= 1) {
        int t2 = (tid >= off) ? sh[tid - off] : 0;
        __syncthreads();
        sh[tid] += t2;
        __syncthreads();
    }
    if (idx < NV) g_cursor[idx] = sh[tid] - v;   // exclusive within chunk
    if (tid == CHUNK - 1) g_csum[blockIdx.x] = sh[tid];
}

__global__ void k_scan2() {   // single thread: exclusive scan of 98 chunk totals
    int run = 0;
    for (int i = 0; i < NCH; i++) { int c = g_csum[i]; g_csum[i] = run; run += c; }
}

__global__ void __launch_bounds__(CHUNK)
k_fixup() {
    int idx = blockIdx.x * CHUNK + threadIdx.x;
    if (idx < NV) g_cursor[idx] += g_csum[idx >> 10];
}

__global__ void __launch_bounds__(NT)
k_place(const int* __restrict__ dst) {
    int t = blockIdx.x * NT + threadIdx.x;
    for (int e = t; e < NE; e += GS_STRIDE) {
        int p = atomicAdd(&g_cursor[__ldg(dst + e)], 1);
        g_perm[p] = e;
    }
}

// gather original arrays into sorted order; also pack M into float4
__global__ void __launch_bounds__(NT)
k_permute(const int* __restrict__ src, const int* __restrict__ dst,
          const float* __restrict__ H, const float* __restrict__ M,
          float4* __restrict__ M0) {
    int t = blockIdx.x * NT + threadIdx.x;
    for (int i = t; i < NV; i += GS_STRIDE)
        M0[i] = make_float4(M[3 * i], M[3 * i + 1], M[3 * i + 2], 0.f);
    for (int i = t; i < NE; i += GS_STRIDE) {
        int e = g_perm[i];
        g_srcs[i] = __ldg(src + e);
        g_dsts[i] = __ldg(dst + e);
        g_Hs[3 * i + 0] = __ldg(H + 3 * e + 0);
        g_Hs[3 * i + 1] = __ldg(H + 3 * e + 1);
        g_Hs[3 * i + 2] = __ldg(H + 3 * e + 2);
    }
}

// ================= phase A: gather + e-MLP layer1 + zm, e-stats =================
__global__ void __launch_bounds__(NT)
k_A(const float4* __restrict__ M, float4* __restrict__ Mn, float* __restrict__ statsOut) {
    int t = blockIdx.x * NT + threadIdx.x;
    for (int i = t; i < NV; i += GS_STRIDE) Mn[i] = make_float4(0.f, 0.f, 0.f, 0.f);

    int base = 4 * t;
    bool valid = base < NE;
    float acc[8] = {0.f,0.f,0.f,0.f,0.f,0.f,0.f,0.f};
    if (valid) {
        int4 s4 = __ldg((const int4*)(g_srcs + base));
        int4 d4 = __ldg((const int4*)(g_dsts + base));
        float4 mi[4], mj[4];
        mi[0] = __ldg(M + d4.x); mi[1] = __ldg(M + d4.y); mi[2] = __ldg(M + d4.z); mi[3] = __ldg(M + d4.w);
        mj[0] = __ldg(M + s4.x); mj[1] = __ldg(M + s4.y); mj[2] = __ldg(M + s4.z); mj[3] = __ldg(M + s4.w);
        float4 ha = __ldg((const float4*)(g_Hs + 3 * base));
        float4 hb = __ldg((const float4*)(g_Hs + 3 * base + 4));
        float4 hc = __ldg((const float4*)(g_Hs + 3 * base + 8));
        float hh[12] = {ha.x,ha.y,ha.z,ha.w, hb.x,hb.y,hb.z,hb.w, hc.x,hc.y,hc.z,hc.w};
        float zz[12];
#pragma unroll
        for (int k = 0; k < 4; k++) {
            float h0 = hh[3*k], h1 = hh[3*k+1], h2 = hh[3*k+2];
            float y[4];
#pragma unroll
            for (int j = 0; j < 4; j++) {
                y[j] = cw.we_b1[j]
                     + mi[k].x * cw.we_w1[0*4+j] + mi[k].y * cw.we_w1[1*4+j] + mi[k].z * cw.we_w1[2*4+j]
                     + mj[k].x * cw.we_w1[3*4+j] + mj[k].y * cw.we_w1[4*4+j] + mj[k].z * cw.we_w1[5*4+j]
                     + h0 * cw.we_w1[6*4+j] + h1 * cw.we_w1[7*4+j] + h2 * cw.we_w1[8*4+j];
                acc[j] += y[j];
                acc[4+j] += y[j] * y[j];
            }
            g_Y[base + k] = make_float4(y[0], y[1], y[2], y[3]);
#pragma unroll
            for (int c = 0; c < 3; c++) {
                zz[3*k+c] = cw.wv_b1[c]
                    + mi[k].x * cw.wv_w1[0*3+c] + mi[k].y * cw.wv_w1[1*3+c] + mi[k].z * cw.wv_w1[2*3+c];
            }
        }
        float4* Zp = (float4*)(g_Z + 3 * base);
        Zp[0] = make_float4(zz[0],zz[1],zz[2],zz[3]);
        Zp[1] = make_float4(zz[4],zz[5],zz[6],zz[7]);
        Zp[2] = make_float4(zz[8],zz[9],zz[10],zz[11]);
    }
    block_atomic_add<8>(statsOut, acc);
}

// ================= phase B: e-BN -> Hn -> z, v-stats =================
__global__ void __launch_bounds__(NT)
k_B(const float* __restrict__ statsIn, float* __restrict__ statsOut,
    float* __restrict__ headStats, int doHead) {
    float sc[4], sh[4];
#pragma unroll
    for (int j = 0; j < 4; j++) {
        float m = statsIn[j] * (1.f / NE);
        float v = statsIn[4+j] * (1.f / NE) - m * m;
        float r = rsqrtf(v + BN_EPS);
        sc[j] = r * cw.we_g1[j];
        sh[j] = cw.we_be1[j] - m * sc[j];
    }
    int t = blockIdx.x * NT + threadIdx.x;
    int base = 4 * t;
    bool valid = base < NE;
    float acc[6] = {0.f,0.f,0.f,0.f,0.f,0.f};
    float hacc[6] = {0.f,0.f,0.f,0.f,0.f,0.f};
    if (valid) {
        float4 y4[4];
#pragma unroll
        for (int k = 0; k < 4; k++) y4[k] = __ldg(g_Y + base + k);
        const float4* Zp = (const float4*)(g_Z + 3 * base);
        float4 za = Zp[0], zb = Zp[1], zc = Zp[2];
        float zm[12] = {za.x,za.y,za.z,za.w, zb.x,zb.y,zb.z,zb.w, zc.x,zc.y,zc.z,zc.w};
        float hhn[12], zzn[12];
#pragma unroll
        for (int k = 0; k < 4; k++) {
            float tj[4];
            tj[0] = fmaxf(fmaf(y4[k].x, sc[0], sh[0]), 0.f);
            tj[1] = fmaxf(fmaf(y4[k].y, sc[1], sh[1]), 0.f);
            tj[2] = fmaxf(fmaf(y4[k].z, sc[2], sh[2]), 0.f);
            tj[3] = fmaxf(fmaf(y4[k].w, sc[3], sh[3]), 0.f);
            float hn[3];
#pragma unroll
            for (int c = 0; c < 3; c++) {
                hn[c] = cw.we_b2[c]
                      + tj[0]*cw.we_w2[0*3+c] + tj[1]*cw.we_w2[1*3+c]
                      + tj[2]*cw.we_w2[2*3+c] + tj[3]*cw.we_w2[3*3+c];
                hhn[3*k+c] = hn[c];
            }
#pragma unroll
            for (int c = 0; c < 3; c++) {
                float z = zm[3*k+c]
                        + hn[0]*cw.wv_w1[3*3+c] + hn[1]*cw.wv_w1[4*3+c] + hn[2]*cw.wv_w1[5*3+c];
                zzn[3*k+c] = z;
                acc[c] += z;
                acc[3+c] += z * z;
            }
            if (doHead) {
#pragma unroll
                for (int c = 0; c < 3; c++) {
                    float yh = cw.ob1[c]
                             + hn[0]*cw.ow1[0*3+c] + hn[1]*cw.ow1[1*3+c] + hn[2]*cw.ow1[2*3+c];
                    hacc[c] += yh;
                    hacc[3+c] += yh * yh;
                }
            }
        }
        float4* Hp = (float4*)(g_Hs + 3 * base);
        Hp[0] = make_float4(hhn[0],hhn[1],hhn[2],hhn[3]);
        Hp[1] = make_float4(hhn[4],hhn[5],hhn[6],hhn[7]);
        Hp[2] = make_float4(hhn[8],hhn[9],hhn[10],hhn[11]);
        float4* Zo = (float4*)(g_Z + 3 * base);
        Zo[0] = make_float4(zzn[0],zzn[1],zzn[2],zzn[3]);
        Zo[1] = make_float4(zzn[4],zzn[5],zzn[6],zzn[7]);
        Zo[2] = make_float4(zzn[8],zzn[9],zzn[10],zzn[11]);
    }
    block_atomic_add<6>(statsOut, acc);
    if (doHead) block_atomic_add<6>(headStats, hacc);
}

// ================= phase C: v-BN -> message -> run-merged scatter =================
__global__ void __launch_bounds__(NT)
k_C(float4* __restrict__ Mn, const float* __restrict__ statsIn) {
    float sc[3], sh[3];
#pragma unroll
    for (int c = 0; c < 3; c++) {
        float m = statsIn[c] * (1.f / NE);
        float v = statsIn[3+c] * (1.f / NE) - m * m;
        float r = rsqrtf(v + BN_EPS);
        sc[c] = r * cw.wv_g1[c];
        sh[c] = cw.wv_be1[c] - m * sc[c];
    }
    int t = blockIdx.x * NT + threadIdx.x;
    int base = 4 * t;
    if (base >= NE) return;
    int4 d4 = __ldg((const int4*)(g_dsts + base));
    const float4* Zp = (const float4*)(g_Z + 3 * base);
    float4 za = Zp[0], zb = Zp[1], zc = Zp[2];
    float zz[12] = {za.x,za.y,za.z,za.w, zb.x,zb.y,zb.z,zb.w, zc.x,zc.y,zc.z,zc.w};
    int ids[4] = {d4.x, d4.y, d4.z, d4.w};
    float msg[4][3];
#pragma unroll
    for (int k = 0; k < 4; k++) {
        float t0 = fmaxf(fmaf(zz[3*k+0], sc[0], sh[0]), 0.f);
        float t1 = fmaxf(fmaf(zz[3*k+1], sc[1], sh[1]), 0.f);
        float t2 = fmaxf(fmaf(zz[3*k+2], sc[2], sh[2]), 0.f);
        msg[k][0] = cw.wv_b2[0] + t0*cw.wv_w2[0] + t1*cw.wv_w2[3] + t2*cw.wv_w2[6];
        msg[k][1] = cw.wv_b2[1] + t0*cw.wv_w2[1] + t1*cw.wv_w2[4] + t2*cw.wv_w2[7];
        msg[k][2] = cw.wv_b2[2] + t0*cw.wv_w2[2] + t1*cw.wv_w2[5] + t2*cw.wv_w2[8];
    }
    // run-merge consecutive equal dst (edges sorted by dst)
    int cur = ids[0];
    float a0 = msg[0][0], a1 = msg[0][1], a2 = msg[0][2];
#pragma unroll
    for (int k = 1; k < 4; k++) {
        if (ids[k] == cur) {
            a0 += msg[k][0]; a1 += msg[k][1]; a2 += msg[k][2];
        } else {
            float* p = (float*)(Mn + cur);
            asm volatile("red.global.add.v4.f32 [%0], {%1,%2,%3,%4};"
                         :: "l"(p), "f"(a0), "f"(a1), "f"(a2), "f"(0.f) : "memory");
            cur = ids[k]; a0 = msg[k][0]; a1 = msg[k][1]; a2 = msg[k][2];
        }
    }
    float* p = (float*)(Mn + cur);
    asm volatile("red.global.add.v4.f32 [%0], {%1,%2,%3,%4};"
                 :: "l"(p), "f"(a0), "f"(a1), "f"(a2), "f"(0.f) : "memory");
}

// ================= head =================
__global__ void __launch_bounds__(NT)
kh_out(const float* __restrict__ statsIn, float* __restrict__ out) {
    float sc[3], sh[3];
#pragma unroll
    for (int c = 0; c < 3; c++) {
        float m = statsIn[c] * (1.f / NE);
        float v = statsIn[3+c] * (1.f / NE) - m * m;
        float r = rsqrtf(v + BN_EPS);
        sc[c] = r * cw.og[c];
        sh[c] = cw.obe[c] - m * sc[c];
    }
    int t = blockIdx.x * NT + threadIdx.x;
    int base = 4 * t;
    if (base >= NE) return;
    int4 p4 = __ldg((const int4*)(g_perm + base));
    int pp[4] = {p4.x, p4.y, p4.z, p4.w};
    const float4* Hp = (const float4*)(g_Hs + 3 * base);
    float4 ha = Hp[0], hb = Hp[1], hc = Hp[2];
    float hh[12] = {ha.x,ha.y,ha.z,ha.w, hb.x,hb.y,hb.z,hb.w, hc.x,hc.y,hc.z,hc.w};
#pragma unroll
    for (int k = 0; k < 4; k++) {
        float tc[3];
#pragma unroll
        for (int c = 0; c < 3; c++) {
            float y = cw.ob1[c]
                    + hh[3*k]*cw.ow1[0*3+c] + hh[3*k+1]*cw.ow1[1*3+c] + hh[3*k+2]*cw.ow1[2*3+c];
            tc[c] = fmaxf(fmaf(y, sc[c], sh[c]), 0.f);
        }
        float l0 = cw.ob2[0] + tc[0]*cw.ow2[0] + tc[1]*cw.ow2[2] + tc[2]*cw.ow2[4];
        float l1 = cw.ob2[1] + tc[0]*cw.ow2[1] + tc[1]*cw.ow2[3] + tc[2]*cw.ow2[5];
        float mx = fmaxf(l0, l1);
        float e0 = __expf(l0 - mx);
        float e1 = __expf(l1 - mx);
        float inv = 1.f / (e0 + e1);
        ((float2*)out)[pp[k]] = make_float2(e0 * inv, e1 * inv);
    }
}

extern "C" void kernel_launch(void* const* d_in, const int* in_sizes, int n_in,
                              void* d_out, int out_size) {
    const float* M  = (const float*)d_in[0];
    const float* H  = (const float*)d_in[1];
    const int*   ei = (const int*)d_in[2];
    const int*   src = ei;
    const int*   dst = ei + NE;

    cudaMemcpyToSymbolAsync(cw, d_in[3],  36*4, offsetof(CW, we_w1), cudaMemcpyDeviceToDevice);
    cudaMemcpyToSymbolAsync(cw, d_in[4],   4*4, offsetof(CW, we_b1), cudaMemcpyDeviceToDevice);
    cudaMemcpyToSymbolAsync(cw, d_in[5],   4*4, offsetof(CW, we_g1), cudaMemcpyDeviceToDevice);
    cudaMemcpyToSymbolAsync(cw, d_in[6],   4*4, offsetof(CW, we_be1), cudaMemcpyDeviceToDevice);
    cudaMemcpyToSymbolAsync(cw, d_in[7],  12*4, offsetof(CW, we_w2), cudaMemcpyDeviceToDevice);
    cudaMemcpyToSymbolAsync(cw, d_in[8],   3*4, offsetof(CW, we_b2), cudaMemcpyDeviceToDevice);
    cudaMemcpyToSymbolAsync(cw, d_in[9],  18*4, offsetof(CW, wv_w1), cudaMemcpyDeviceToDevice);
    cudaMemcpyToSymbolAsync(cw, d_in[10],  3*4, offsetof(CW, wv_b1), cudaMemcpyDeviceToDevice);
    cudaMemcpyToSymbolAsync(cw, d_in[11],  3*4, offsetof(CW, wv_g1), cudaMemcpyDeviceToDevice);
    cudaMemcpyToSymbolAsync(cw, d_in[12],  3*4, offsetof(CW, wv_be1), cudaMemcpyDeviceToDevice);
    cudaMemcpyToSymbolAsync(cw, d_in[13],  9*4, offsetof(CW, wv_w2), cudaMemcpyDeviceToDevice);
    cudaMemcpyToSymbolAsync(cw, d_in[14],  3*4, offsetof(CW, wv_b2), cudaMemcpyDeviceToDevice);
    cudaMemcpyToSymbolAsync(cw, d_in[15],  9*4, offsetof(CW, ow1), cudaMemcpyDeviceToDevice);
    cudaMemcpyToSymbolAsync(cw, d_in[16],  3*4, offsetof(CW, ob1), cudaMemcpyDeviceToDevice);
    cudaMemcpyToSymbolAsync(cw, d_in[17],  3*4, offsetof(CW, og), cudaMemcpyDeviceToDevice);
    cudaMemcpyToSymbolAsync(cw, d_in[18],  3*4, offsetof(CW, obe), cudaMemcpyDeviceToDevice);
    cudaMemcpyToSymbolAsync(cw, d_in[19],  6*4, offsetof(CW, ow2), cudaMemcpyDeviceToDevice);
    cudaMemcpyToSymbolAsync(cw, d_in[20],  2*4, offsetof(CW, ob2), cudaMemcpyDeviceToDevice);

    float4 *gM0, *gM1; float* gStats; void* p;
    cudaGetSymbolAddress(&p, g_M);     gM0 = (float4*)p; gM1 = gM0 + NV;
    cudaGetSymbolAddress(&p, g_stats); gStats = (float*)p;
    cudaMemsetAsync(gStats, 0, sizeof(float) * 22 * 16);
    cudaGetSymbolAddress(&p, g_hist);
    cudaMemsetAsync(p, 0, sizeof(int) * NV);

    // ---- counting sort by dst ----
    k_hist<<<NBLK, NT>>>(dst);
    k_scan1<<<NCH, CHUNK>>>();
    k_scan2<<<1, 1>>>();
    k_fixup<<<NCH, CHUNK>>>();
    k_place<<<NBLK, NT>>>(dst);
    k_permute<<<NBLK, NT>>>(src, dst, H, M, gM0);

    for (int l = 0; l < NLAYER; l++) {
        float4* Mc = (l & 1) ? gM1 : gM0;
        float4* Mn = (l & 1) ? gM0 : gM1;
        float* se = gStats + l * 16;
        float* sv = gStats + l * 16 + 8;
        k_A<<<NBLK, NT>>>(Mc, Mn, se);
        k_B<<<NBLK, NT>>>(se, sv, gStats + 20 * 16, (l == NLAYER - 1) ? 1 : 0);
        k_C<<<NBLK, NT>>>(Mn, sv);
    }
    kh_out<<<NBLK, NT>>>(gStats + 20 * 16, (float*)d_out);
}